// round 15
// baseline (speedup 1.0000x reference)
#include <cuda_runtime.h>
#include <cuda_fp16.h>
#include <cstdint>

// ---------------------------------------------------------------------------
// involution_81106162418291 — MMA k1 + 256-thread k2:
//   8 GEMM warps (2 m-tiles each), involution split across ky-halves with
//   shfl combine; 3 CTAs/SM x 24 warps.
// B=4, C=256, H=W=56, GC=4 -> G=64, K=7 -> K2=49, Cr=64, stride=1, pad=3
// ---------------------------------------------------------------------------

#define Bsz 4
#define C    256
#define Cr   64
#define HW   3136
#define Hdim 56
#define G    64
#define K2   49

__device__ __half g_yh[Bsz * HW * Cr];     // y fp16, [b][hw][cr]

__device__ __forceinline__ uint32_t smem_u32(const void* p) {
    uint32_t a;
    asm("{ .reg .u64 t; cvta.to.shared.u64 t, %1; cvt.u32.u64 %0, t; }"
        : "=r"(a) : "l"(p));
    return a;
}
__device__ __forceinline__ uint32_t prmt5432(uint32_t a, uint32_t b) {
    uint32_t d;
    asm("prmt.b32 %0, %1, %2, 0x5432;" : "=r"(d) : "r"(a), "r"(b));
    return d;
}

#define LDSM_X4(r0,r1,r2,r3,addr) \
    asm volatile("ldmatrix.sync.aligned.m8n8.x4.shared.b16 {%0,%1,%2,%3}, [%4];" \
        : "=r"(r0),"=r"(r1),"=r"(r2),"=r"(r3) : "r"(addr))
#define LDSM_X4_T(r0,r1,r2,r3,addr) \
    asm volatile("ldmatrix.sync.aligned.m8n8.x4.trans.shared.b16 {%0,%1,%2,%3}, [%4];" \
        : "=r"(r0),"=r"(r1),"=r"(r2),"=r"(r3) : "r"(addr))
#define LDSM_X2(r0,r1,addr) \
    asm volatile("ldmatrix.sync.aligned.m8n8.x2.shared.b16 {%0,%1}, [%2];" \
        : "=r"(r0),"=r"(r1) : "r"(addr))
#define MMA16816(c,a,b) \
    asm volatile("mma.sync.aligned.m16n8k16.row.col.f32.f16.f16.f32 " \
        "{%0,%1,%2,%3}, {%4,%5,%6,%7}, {%8,%9}, {%0,%1,%2,%3};" \
        : "+f"((c)[0]),"+f"((c)[1]),"+f"((c)[2]),"+f"((c)[3]) \
        : "r"((a)[0]),"r"((a)[1]),"r"((a)[2]),"r"((a)[3]), "r"((b)[0]),"r"((b)[1]))
#define CP_ASYNC16(dst, src) \
    asm volatile("cp.async.cg.shared.global [%0], [%1], 16;" :: "r"(dst), "l"(src))
#define CP_COMMIT() asm volatile("cp.async.commit_group;")
#define CP_WAIT(n)  asm volatile("cp.async.wait_group %0;" :: "n"(n))

// ---------------------------------------------------------------------------
// k1 (MMA): y[px,cr] = relu(BN-folded w1 . x), fp16 out. grid (49,4), 256 thr.
// ---------------------------------------------------------------------------
__global__ void __launch_bounds__(256) k1_mma(
    const float* __restrict__ x,  const float* __restrict__ w1,
    const float* __restrict__ b1, const float* __restrict__ gamma,
    const float* __restrict__ beta, const float* __restrict__ mean,
    const float* __restrict__ var)
{
    __shared__ __align__(16) __half w1s[4][64 * 72];  // [chunk][cr][c'] 144B pitch
    __shared__ __align__(16) __half xs[64 * 72];      // [c'][px] 144B pitch
    __shared__ float invs[64], biass[64];

    const int tid = threadIdx.x, lane = tid & 31, wid = tid >> 5;
    const int pxq = wid & 3, crh = wid >> 2;
    const int b  = blockIdx.y;
    const int P0 = blockIdx.x * 64;
    const uint32_t sw1 = smem_u32(w1s);
    const uint32_t sxs = smem_u32(xs);

    if (tid < 64) {
        float inv = gamma[tid] * rsqrtf(var[tid] + 1e-5f);
        invs[tid]  = inv;
        biass[tid] = b1[tid] * inv + beta[tid] - mean[tid] * inv;
    }
    __syncthreads();

    for (int idx = tid; idx < 64 * 32; idx += 256) {
        int cr = idx >> 5, jg = idx & 31;
        float inv = invs[cr];
        const float4* src = (const float4*)(w1 + cr * 256 + jg * 8);
        float4 v0 = src[0], v1 = src[1];
        __half2 h0 = __floats2half2_rn(v0.x * inv, v0.y * inv);
        __half2 h1 = __floats2half2_rn(v0.z * inv, v0.w * inv);
        __half2 h2 = __floats2half2_rn(v1.x * inv, v1.y * inv);
        __half2 h3 = __floats2half2_rn(v1.z * inv, v1.w * inv);
        uint4 pk;
        pk.x = *(uint32_t*)&h0; pk.y = *(uint32_t*)&h1;
        pk.z = *(uint32_t*)&h2; pk.w = *(uint32_t*)&h3;
        *(uint4*)((char*)w1s + (jg >> 3) * 9216 + cr * 144 + (jg & 7) * 16) = pk;
    }

    float acc[4][4];
#pragma unroll
    for (int nt = 0; nt < 4; nt++)
#pragma unroll
        for (int i = 0; i < 4; i++) acc[nt][i] = 0.f;

    const uint32_t atoff = ((uint32_t)((lane & 7) + ((lane >> 4) << 3)) * 144
                         + (uint32_t)(pxq * 16 + ((lane >> 3) & 1) * 8) * 2);
    const uint32_t bboff = ((uint32_t)(lane & 7) * 144
                         + (uint32_t)((lane >> 3) & 1) * 16);

    for (int kc = 0; kc < 4; kc++) {
        __syncthreads();
        const float* xc = x + (size_t)(b * C + kc * 64) * HW + P0;
#pragma unroll
        for (int it = 0; it < 4; it++) {
            int idx = it * 256 + tid;
            int r = idx >> 4, pg = idx & 15;
            float4 v = *(const float4*)(xc + (size_t)r * HW + pg * 4);
            __half2 h0 = __floats2half2_rn(v.x, v.y);
            __half2 h1 = __floats2half2_rn(v.z, v.w);
            uint2 pk;
            pk.x = *(uint32_t*)&h0; pk.y = *(uint32_t*)&h1;
            *(uint2*)((char*)xs + r * 144 + pg * 8) = pk;
        }
        __syncthreads();

        uint32_t a[4][4];
#pragma unroll
        for (int kk = 0; kk < 4; kk++)
            LDSM_X4_T(a[kk][0], a[kk][1], a[kk][2], a[kk][3],
                      sxs + atoff + (uint32_t)(kk * 16 * 144));

        const uint32_t bc = sw1 + (uint32_t)(kc * 9216) + bboff
                          + (uint32_t)(crh * 32 * 144);
#pragma unroll
        for (int kk = 0; kk < 4; kk++)
#pragma unroll
            for (int nt = 0; nt < 4; nt++) {
                uint32_t b0, b1r;
                LDSM_X2(b0, b1r, bc + (uint32_t)(nt * 8 * 144 + kk * 32));
                uint32_t bw[2] = {b0, b1r};
                MMA16816(acc[nt], a[kk], bw);
            }
    }

#pragma unroll
    for (int nt = 0; nt < 4; nt++) {
        int cr  = crh * 32 + nt * 8 + (lane & 3) * 2;
        int px0 = P0 + pxq * 16 + (lane >> 2);
        float bb0 = biass[cr], bb1 = biass[cr + 1];
        __half2 h0 = __floats2half2_rn(fmaxf(acc[nt][0] + bb0, 0.f),
                                       fmaxf(acc[nt][1] + bb1, 0.f));
        __half2 h1 = __floats2half2_rn(fmaxf(acc[nt][2] + bb0, 0.f),
                                       fmaxf(acc[nt][3] + bb1, 0.f));
        *(__half2*)(g_yh + (size_t)(b * HW + px0) * Cr + cr)       = h0;
        *(__half2*)(g_yh + (size_t)(b * HW + px0 + 8) * Cr + cr)   = h1;
    }
}

// ---------------------------------------------------------------------------
// k2: grid (7,4,64), 256 thr, 3 CTAs/SM (24 warps).
//   GEMM: warp = (mh 0..1, nq 0..3): 2 m-tiles x 16 px.
//   Involution: warp = (ch 0..3, pp-half); lane = (pp-low, ky-half);
//   shfl_xor(16) combines ky 0..3 with ky 4..6.
// smem (50432B): A@0 9216 | B@9216 2x9216 | wts16@27648 2x7168 |
//                xs16@41984 8064 | b2s@50176
// ---------------------------------------------------------------------------
#define S_A   0u
#define S_B   9216u
#define S_WTS 27648u
#define S_XS  41984u
#define S_B2  50176u
#define SMEM_K2 50432

__global__ void __launch_bounds__(256, 3) k2_involution(
    const float* __restrict__ x,  const float* __restrict__ w2,
    const float* __restrict__ b2, float* __restrict__ out)
{
    extern __shared__ __align__(16) char buf[];
    const uint32_t sb = smem_u32(buf);
    const int tid = threadIdx.x, wid = tid >> 5, lane = tid & 31;
    const int mh = wid & 1, nq = wid >> 1;   // GEMM roles
    const int b  = blockIdx.y;
    const int g  = blockIdx.z;
    const int h0 = blockIdx.x * 8;

    __half* xs16 = (__half*)(buf + S_XS);
    float*  b2s  = (float*)(buf + S_B2);

    // ---- stage A: w2 fp32 -> fp16 (49 rows x 64, pitch 144B) ----
    for (int idx = tid; idx < K2 * 8; idx += 256) {
        int r = idx >> 3, j = idx & 7;
        const float4* src = (const float4*)(w2 + (size_t)(g * K2 + r) * Cr + j * 8);
        float4 v0 = src[0], v1 = src[1];
        __half2 h0h = __floats2half2_rn(v0.x, v0.y);
        __half2 h1h = __floats2half2_rn(v0.z, v0.w);
        __half2 h2h = __floats2half2_rn(v1.x, v1.y);
        __half2 h3h = __floats2half2_rn(v1.z, v1.w);
        uint4 pk;
        pk.x = *(uint32_t*)&h0h; pk.y = *(uint32_t*)&h1h;
        pk.z = *(uint32_t*)&h2h; pk.w = *(uint32_t*)&h3h;
        *(uint4*)(buf + S_A + (uint32_t)(r * 144 + j * 16)) = pk;
    }
    for (int idx = tid; idx < 15 * 9; idx += 256) {
        int r = 49 + idx / 9, j = idx % 9;
        *(uint4*)(buf + S_A + (uint32_t)(r * 144 + j * 16)) = make_uint4(0, 0, 0, 0);
    }
    if (tid < K2) b2s[tid] = b2[g * K2 + tid];
    for (int idx = tid; idx < 4 * 14 * 62; idx += 256) {
        int ch = idx / 868, rem = idx - ch * 868;
        int r = rem / 62, col = rem - r * 62;
        int hh = h0 + r - 3, ww = col - 3;
        float v = 0.f;
        if (hh >= 0 && hh < Hdim && ww >= 0 && ww < Hdim)
            v = x[((size_t)(b * C + g * 4 + ch) * Hdim + hh) * Hdim + ww];
        xs16[(ch * 14 + r) * 72 + col] = __float2half(v);
    }

    const char* yhp = (const char*)g_yh;
    auto stage_B = [&](int tw, int q) {
#pragma unroll
        for (int it = 0; it < 2; it++) {
            int idx = it * 256 + tid;
            int n = idx >> 3, j = idx & 7;
            int hw = (h0 + (n >> 3)) * Hdim + tw * 8 + (n & 7);
            uint32_t dst = sb + S_B + (uint32_t)(q * 9216 + n * 144 + j * 16);
            CP_ASYNC16(dst, yhp + (size_t)(b * HW + hw) * 128 + j * 16);
        }
    };

    stage_B(0, 0);
    CP_COMMIT();
    __syncthreads();

    // ---- ldmatrix A fragments: 2 m-tiles per warp (rows mh*32..mh*32+31) ----
    uint32_t ah[2][4][4];
    const uint32_t aoff = ((uint32_t)(lane & 15) * 72 + (uint32_t)(lane >> 4) * 8) * 2;
#pragma unroll
    for (int mt = 0; mt < 2; mt++) {
        uint32_t rowb = (uint32_t)((mh * 2 + mt) * 16 * 144);
#pragma unroll
        for (int kk = 0; kk < 4; kk++)
            LDSM_X4(ah[mt][kk][0], ah[mt][kk][1], ah[mt][kk][2], ah[mt][kk][3],
                    sb + S_A + aoff + rowb + (uint32_t)(kk * 32));
    }

    const uint32_t boff = ((uint32_t)(nq * 16 + (lane & 7)) * 72
                         + (uint32_t)((lane >> 3) & 1) * 8) * 2;

    // involution mapping: warp = (ch, pp-half); lane = (pp-low, ky-half)
    const int chw = wid & 3;             // channel 0..3
    const int pp  = (wid >> 2) * 16 + (lane & 15);   // px-pair 0..31
    const int kyh = lane >> 4;           // 0: ky 0..3, 1: ky 4..6
    const int phi = pp >> 2;
    const int pwi = (pp & 3) * 2;

    for (int tw = 0; tw < 7; tw++) {
        const int q  = tw & 1;
        const int w0 = tw * 8;

        if (tw < 6) {
            stage_B(tw + 1, q ^ 1);
            CP_COMMIT();
            CP_WAIT(1);
        } else {
            CP_WAIT(0);
        }
        __syncthreads();   // B(tw) visible

        // ---- GEMM: 2 m-tiles x 2 n-tiles per warp ----
        const uint32_t bhi = sb + S_B + (uint32_t)(q * 9216);
        float c[2][2][4];
#pragma unroll
        for (int mt = 0; mt < 2; mt++)
#pragma unroll
            for (int nt = 0; nt < 2; nt++)
#pragma unroll
                for (int i = 0; i < 4; i++) c[mt][nt][i] = 0.f;

#pragma unroll
        for (int kk = 0; kk < 4; kk++) {
            uint32_t bh[2][2];
#pragma unroll
            for (int nt = 0; nt < 2; nt++) {
                uint32_t o = boff + (uint32_t)(nt * 8 * 144 + kk * 32);
                LDSM_X2(bh[nt][0], bh[nt][1], bhi + o);
            }
#pragma unroll
            for (int mt = 0; mt < 2; mt++)
#pragma unroll
                for (int nt = 0; nt < 2; nt++)
                    MMA16816(c[mt][nt], ah[mt][kk], bh[nt]);
        }

        // ---- epilogue: (c+bias) -> half2 -> wts16[q] ----
        __half* wtsq = (__half*)(buf + S_WTS + (uint32_t)(q * 7168));
#pragma unroll
        for (int mt = 0; mt < 2; mt++) {
            int r0 = (mh * 2 + mt) * 16 + (lane >> 2);
            int r1 = r0 + 8;
#pragma unroll
            for (int nt = 0; nt < 2; nt++) {
                int col = nq * 16 + nt * 8 + (lane & 3) * 2;
                if (r0 < K2) {
                    float bias = b2s[r0];
                    __half2 h = __floats2half2_rn(c[mt][nt][0] + bias,
                                                  c[mt][nt][1] + bias);
                    *(__half2*)(wtsq + r0 * 72 + col) = h;
                }
                if (r1 < K2) {
                    float bias = b2s[r1];
                    __half2 h = __floats2half2_rn(c[mt][nt][2] + bias,
                                                  c[mt][nt][3] + bias);
                    *(__half2*)(wtsq + r1 * 72 + col) = h;
                }
            }
        }
        __syncthreads();   // wts16[q] visible

        // ---- involution: ky-half per lane-half, HFMA2, shfl combine ----
        float s0 = 0.f, s1 = 0.f;
        const int ky0 = kyh ? 4 : 0;
        const int kyn = kyh ? 3 : 4;
        for (int kyi = 0; kyi < kyn; kyi++) {
            int ky = ky0 + kyi;
            const uint32_t* xrow = (const uint32_t*)(xs16
                + (chw * 14 + phi + ky) * 72 + w0 + pwi);
            uint32_t x01 = xrow[0], x23 = xrow[1], x45 = xrow[2], x67 = xrow[3];
            uint32_t xp[7];
            xp[0] = x01;
            xp[1] = prmt5432(x01, x23);
            xp[2] = x23;
            xp[3] = prmt5432(x23, x45);
            xp[4] = x45;
            xp[5] = prmt5432(x45, x67);
            xp[6] = x67;
            const __half2* wrow = (const __half2*)(wtsq + (ky * 7) * 72) + pp;
            __half2 acc = __floats2half2_rn(0.f, 0.f);
#pragma unroll
            for (int kx = 0; kx < 7; kx++)
                acc = __hfma2(wrow[kx * 36], *(const __half2*)&xp[kx], acc);
            float2 t = __half22float2(acc);
            s0 += t.x;
            s1 += t.y;
        }
        s0 += __shfl_xor_sync(0xffffffffu, s0, 16);
        s1 += __shfl_xor_sync(0xffffffffu, s1, 16);
        if (kyh == 0) {
            *(float2*)(out + ((size_t)(b * C + g * 4 + chw) * Hdim + h0 + phi) * Hdim
                       + w0 + pwi) = make_float2(s0, s1);
        }
    }
}

extern "C" void kernel_launch(void* const* d_in, const int* in_sizes, int n_in,
                              void* d_out, int out_size)
{
    const float* x     = (const float*)d_in[0];
    const float* w1    = (const float*)d_in[1];
    const float* b1    = (const float*)d_in[2];
    const float* gamma = (const float*)d_in[3];
    const float* beta  = (const float*)d_in[4];
    const float* mean  = (const float*)d_in[5];
    const float* var   = (const float*)d_in[6];
    const float* w2    = (const float*)d_in[7];
    const float* b2    = (const float*)d_in[8];
    float* out = (float*)d_out;

    cudaFuncSetAttribute(k2_involution,
                         cudaFuncAttributeMaxDynamicSharedMemorySize, SMEM_K2);

    dim3 g1(49, 4);
    k1_mma<<<g1, 256>>>(x, w1, b1, gamma, beta, mean, var);

    dim3 g2(7, 4, 64);
    k2_involution<<<g2, 256, SMEM_K2>>>(x, w2, b2, out);
}

// round 16
// speedup vs baseline: 1.4185x; 1.4185x over previous
#include <cuda_runtime.h>
#include <cuda_fp16.h>
#include <cstdint>

// ---------------------------------------------------------------------------
// involution_81106162418291 — R14 structure + 1-sync-per-chunk pipeline:
//   k1: MMA conv+BN+relu (fp16 out). k2: fp16 MMA weight GEMM + HFMA2
//   involution, B staged AFTER the chunk sync (safe buffer reuse).
// B=4, C=256, H=W=56, GC=4 -> G=64, K=7 -> K2=49, Cr=64, stride=1, pad=3
// ---------------------------------------------------------------------------

#define Bsz 4
#define C    256
#define Cr   64
#define HW   3136
#define Hdim 56
#define G    64
#define K2   49

__device__ __half g_yh[Bsz * HW * Cr];     // y fp16, [b][hw][cr]

__device__ __forceinline__ uint32_t smem_u32(const void* p) {
    uint32_t a;
    asm("{ .reg .u64 t; cvta.to.shared.u64 t, %1; cvt.u32.u64 %0, t; }"
        : "=r"(a) : "l"(p));
    return a;
}
__device__ __forceinline__ uint32_t prmt5432(uint32_t a, uint32_t b) {
    uint32_t d;
    asm("prmt.b32 %0, %1, %2, 0x5432;" : "=r"(d) : "r"(a), "r"(b));
    return d;
}

#define LDSM_X4(r0,r1,r2,r3,addr) \
    asm volatile("ldmatrix.sync.aligned.m8n8.x4.shared.b16 {%0,%1,%2,%3}, [%4];" \
        : "=r"(r0),"=r"(r1),"=r"(r2),"=r"(r3) : "r"(addr))
#define LDSM_X4_T(r0,r1,r2,r3,addr) \
    asm volatile("ldmatrix.sync.aligned.m8n8.x4.trans.shared.b16 {%0,%1,%2,%3}, [%4];" \
        : "=r"(r0),"=r"(r1),"=r"(r2),"=r"(r3) : "r"(addr))
#define LDSM_X2(r0,r1,addr) \
    asm volatile("ldmatrix.sync.aligned.m8n8.x2.shared.b16 {%0,%1}, [%2];" \
        : "=r"(r0),"=r"(r1) : "r"(addr))
#define MMA16816(c,a,b) \
    asm volatile("mma.sync.aligned.m16n8k16.row.col.f32.f16.f16.f32 " \
        "{%0,%1,%2,%3}, {%4,%5,%6,%7}, {%8,%9}, {%0,%1,%2,%3};" \
        : "+f"((c)[0]),"+f"((c)[1]),"+f"((c)[2]),"+f"((c)[3]) \
        : "r"((a)[0]),"r"((a)[1]),"r"((a)[2]),"r"((a)[3]), "r"((b)[0]),"r"((b)[1]))
#define CP_ASYNC16(dst, src) \
    asm volatile("cp.async.cg.shared.global [%0], [%1], 16;" :: "r"(dst), "l"(src))
#define CP_COMMIT() asm volatile("cp.async.commit_group;")
#define CP_WAIT(n)  asm volatile("cp.async.wait_group %0;" :: "n"(n))

// ---------------------------------------------------------------------------
// k1 (MMA): y[px,cr] = relu(BN-folded w1 . x), fp16 out. grid (49,4), 256 thr.
// ---------------------------------------------------------------------------
__global__ void __launch_bounds__(256) k1_mma(
    const float* __restrict__ x,  const float* __restrict__ w1,
    const float* __restrict__ b1, const float* __restrict__ gamma,
    const float* __restrict__ beta, const float* __restrict__ mean,
    const float* __restrict__ var)
{
    __shared__ __align__(16) __half w1s[4][64 * 72];  // [chunk][cr][c'] 144B pitch
    __shared__ __align__(16) __half xs[64 * 72];      // [c'][px] 144B pitch
    __shared__ float invs[64], biass[64];

    const int tid = threadIdx.x, lane = tid & 31, wid = tid >> 5;
    const int pxq = wid & 3, crh = wid >> 2;
    const int b  = blockIdx.y;
    const int P0 = blockIdx.x * 64;
    const uint32_t sw1 = smem_u32(w1s);
    const uint32_t sxs = smem_u32(xs);

    if (tid < 64) {
        float inv = gamma[tid] * rsqrtf(var[tid] + 1e-5f);
        invs[tid]  = inv;
        biass[tid] = b1[tid] * inv + beta[tid] - mean[tid] * inv;
    }
    __syncthreads();

    for (int idx = tid; idx < 64 * 32; idx += 256) {
        int cr = idx >> 5, jg = idx & 31;
        float inv = invs[cr];
        const float4* src = (const float4*)(w1 + cr * 256 + jg * 8);
        float4 v0 = src[0], v1 = src[1];
        __half2 h0 = __floats2half2_rn(v0.x * inv, v0.y * inv);
        __half2 h1 = __floats2half2_rn(v0.z * inv, v0.w * inv);
        __half2 h2 = __floats2half2_rn(v1.x * inv, v1.y * inv);
        __half2 h3 = __floats2half2_rn(v1.z * inv, v1.w * inv);
        uint4 pk;
        pk.x = *(uint32_t*)&h0; pk.y = *(uint32_t*)&h1;
        pk.z = *(uint32_t*)&h2; pk.w = *(uint32_t*)&h3;
        *(uint4*)((char*)w1s + (jg >> 3) * 9216 + cr * 144 + (jg & 7) * 16) = pk;
    }

    float acc[4][4];
#pragma unroll
    for (int nt = 0; nt < 4; nt++)
#pragma unroll
        for (int i = 0; i < 4; i++) acc[nt][i] = 0.f;

    const uint32_t atoff = ((uint32_t)((lane & 7) + ((lane >> 4) << 3)) * 144
                         + (uint32_t)(pxq * 16 + ((lane >> 3) & 1) * 8) * 2);
    const uint32_t bboff = ((uint32_t)(lane & 7) * 144
                         + (uint32_t)((lane >> 3) & 1) * 16);

    for (int kc = 0; kc < 4; kc++) {
        __syncthreads();
        const float* xc = x + (size_t)(b * C + kc * 64) * HW + P0;
#pragma unroll
        for (int it = 0; it < 4; it++) {
            int idx = it * 256 + tid;
            int r = idx >> 4, pg = idx & 15;
            float4 v = *(const float4*)(xc + (size_t)r * HW + pg * 4);
            __half2 h0 = __floats2half2_rn(v.x, v.y);
            __half2 h1 = __floats2half2_rn(v.z, v.w);
            uint2 pk;
            pk.x = *(uint32_t*)&h0; pk.y = *(uint32_t*)&h1;
            *(uint2*)((char*)xs + r * 144 + pg * 8) = pk;
        }
        __syncthreads();

        uint32_t a[4][4];
#pragma unroll
        for (int kk = 0; kk < 4; kk++)
            LDSM_X4_T(a[kk][0], a[kk][1], a[kk][2], a[kk][3],
                      sxs + atoff + (uint32_t)(kk * 16 * 144));

        const uint32_t bc = sw1 + (uint32_t)(kc * 9216) + bboff
                          + (uint32_t)(crh * 32 * 144);
#pragma unroll
        for (int kk = 0; kk < 4; kk++)
#pragma unroll
            for (int nt = 0; nt < 4; nt++) {
                uint32_t b0, b1r;
                LDSM_X2(b0, b1r, bc + (uint32_t)(nt * 8 * 144 + kk * 32));
                uint32_t bw[2] = {b0, b1r};
                MMA16816(acc[nt], a[kk], bw);
            }
    }

#pragma unroll
    for (int nt = 0; nt < 4; nt++) {
        int cr  = crh * 32 + nt * 8 + (lane & 3) * 2;
        int px0 = P0 + pxq * 16 + (lane >> 2);
        float bb0 = biass[cr], bb1 = biass[cr + 1];
        __half2 h0 = __floats2half2_rn(fmaxf(acc[nt][0] + bb0, 0.f),
                                       fmaxf(acc[nt][1] + bb1, 0.f));
        __half2 h1 = __floats2half2_rn(fmaxf(acc[nt][2] + bb0, 0.f),
                                       fmaxf(acc[nt][3] + bb1, 0.f));
        *(__half2*)(g_yh + (size_t)(b * HW + px0) * Cr + cr)       = h0;
        *(__half2*)(g_yh + (size_t)(b * HW + px0 + 8) * Cr + cr)   = h1;
    }
}

// ---------------------------------------------------------------------------
// k2: R14 layout, ONE sync per chunk. grid (7,4,64), 128 thr, 4 CTAs/SM.
// smem (50432B): A@0 9216 | B@9216 2x9216 | wts16@27648 2x7168 |
//                xs16@41984 8064 | b2s@50176
// Per chunk: GEMM(tw) -> epilogue wts[q] -> CP_WAIT(0) -> sync ->
//            stage_B(tw+2 -> B[q]) -> involution(tw).
// ---------------------------------------------------------------------------
#define S_A   0u
#define S_B   9216u
#define S_WTS 27648u
#define S_XS  41984u
#define S_B2  50176u
#define SMEM_K2 50432

__global__ void __launch_bounds__(128, 4) k2_involution(
    const float* __restrict__ x,  const float* __restrict__ w2,
    const float* __restrict__ b2, float* __restrict__ out)
{
    extern __shared__ __align__(16) char buf[];
    const uint32_t sb = smem_u32(buf);
    const int tid = threadIdx.x, wid = tid >> 5, lane = tid & 31;
    const int nq = wid;
    const int b  = blockIdx.y;
    const int g  = blockIdx.z;
    const int h0 = blockIdx.x * 8;

    __half* xs16 = (__half*)(buf + S_XS);
    float*  b2s  = (float*)(buf + S_B2);

    // ---- stage A: w2 fp32 -> fp16 (49 rows x 64, pitch 144B) ----
    for (int idx = tid; idx < K2 * 8; idx += 128) {
        int r = idx >> 3, j = idx & 7;
        const float4* src = (const float4*)(w2 + (size_t)(g * K2 + r) * Cr + j * 8);
        float4 v0 = src[0], v1 = src[1];
        __half2 h0h = __floats2half2_rn(v0.x, v0.y);
        __half2 h1h = __floats2half2_rn(v0.z, v0.w);
        __half2 h2h = __floats2half2_rn(v1.x, v1.y);
        __half2 h3h = __floats2half2_rn(v1.z, v1.w);
        uint4 pk;
        pk.x = *(uint32_t*)&h0h; pk.y = *(uint32_t*)&h1h;
        pk.z = *(uint32_t*)&h2h; pk.w = *(uint32_t*)&h3h;
        *(uint4*)(buf + S_A + (uint32_t)(r * 144 + j * 16)) = pk;
    }
    for (int idx = tid; idx < 15 * 9; idx += 128) {
        int r = 49 + idx / 9, j = idx % 9;
        *(uint4*)(buf + S_A + (uint32_t)(r * 144 + j * 16)) = make_uint4(0, 0, 0, 0);
    }
    if (tid < K2) b2s[tid] = b2[g * K2 + tid];
    for (int idx = tid; idx < 4 * 14 * 62; idx += 128) {
        int ch = idx / 868, rem = idx - ch * 868;
        int r = rem / 62, col = rem - r * 62;
        int hh = h0 + r - 3, ww = col - 3;
        float v = 0.f;
        if (hh >= 0 && hh < Hdim && ww >= 0 && ww < Hdim)
            v = x[((size_t)(b * C + g * 4 + ch) * Hdim + hh) * Hdim + ww];
        xs16[(ch * 14 + r) * 72 + col] = __float2half(v);
    }

    const char* yhp = (const char*)g_yh;
    auto stage_B = [&](int tw, int q) {
#pragma unroll
        for (int it = 0; it < 4; it++) {
            int idx = it * 128 + tid;
            int n = idx >> 3, j = idx & 7;
            int hw = (h0 + (n >> 3)) * Hdim + tw * 8 + (n & 7);
            uint32_t dst = sb + S_B + (uint32_t)(q * 9216 + n * 144 + j * 16);
            CP_ASYNC16(dst, yhp + (size_t)(b * HW + hw) * 128 + j * 16);
        }
    };

    // prologue: stage B(0), B(1); wait B(0)+B(1); sync covers A/xs/b2s too
    stage_B(0, 0);
    CP_COMMIT();
    stage_B(1, 1);
    CP_COMMIT();
    CP_WAIT(0);
    __syncthreads();

    // ---- ldmatrix A fragments (4 m-tiles, persist across chunks) ----
    uint32_t ah[4][4][4];
    const uint32_t aoff = ((uint32_t)(lane & 15) * 72 + (uint32_t)(lane >> 4) * 8) * 2;
#pragma unroll
    for (int mt = 0; mt < 4; mt++) {
        uint32_t rowb = (uint32_t)(mt * 16 * 144);
#pragma unroll
        for (int kk = 0; kk < 4; kk++)
            LDSM_X4(ah[mt][kk][0], ah[mt][kk][1], ah[mt][kk][2], ah[mt][kk][3],
                    sb + S_A + aoff + rowb + (uint32_t)(kk * 32));
    }

    const uint32_t boff = ((uint32_t)(nq * 16 + (lane & 7)) * 72
                         + (uint32_t)((lane >> 3) & 1) * 8) * 2;

    const int pp  = tid & 31;
    const int chw = tid >> 5;
    const int phi = pp >> 2;
    const int pwi = (pp & 3) * 2;

    for (int tw = 0; tw < 7; tw++) {
        const int q  = tw & 1;
        const int w0 = tw * 8;

        // ---- GEMM(tw): reads B[q] (visible since prev sync) ----
        const uint32_t bhi = sb + S_B + (uint32_t)(q * 9216);
        float c[4][2][4];
#pragma unroll
        for (int mt = 0; mt < 4; mt++)
#pragma unroll
            for (int nt = 0; nt < 2; nt++)
#pragma unroll
                for (int i = 0; i < 4; i++) c[mt][nt][i] = 0.f;

#pragma unroll
        for (int kk = 0; kk < 4; kk++) {
            uint32_t bh[2][2];
#pragma unroll
            for (int nt = 0; nt < 2; nt++) {
                uint32_t o = boff + (uint32_t)(nt * 8 * 144 + kk * 32);
                LDSM_X2(bh[nt][0], bh[nt][1], bhi + o);
            }
#pragma unroll
            for (int mt = 0; mt < 4; mt++)
#pragma unroll
                for (int nt = 0; nt < 2; nt++)
                    MMA16816(c[mt][nt], ah[mt][kk], bh[nt]);
        }

        // ---- epilogue: (c+bias) -> half2 -> wts16[q] ----
        __half* wtsq = (__half*)(buf + S_WTS + (uint32_t)(q * 7168));
#pragma unroll
        for (int mt = 0; mt < 4; mt++) {
            int r0 = mt * 16 + (lane >> 2);
            int r1 = r0 + 8;
#pragma unroll
            for (int nt = 0; nt < 2; nt++) {
                int col = nq * 16 + nt * 8 + (lane & 3) * 2;
                if (r0 < K2) {
                    float bias = b2s[r0];
                    __half2 h = __floats2half2_rn(c[mt][nt][0] + bias,
                                                  c[mt][nt][1] + bias);
                    *(__half2*)(wtsq + r0 * 72 + col) = h;
                }
                if (r1 < K2) {
                    float bias = b2s[r1];
                    __half2 h = __floats2half2_rn(c[mt][nt][2] + bias,
                                                  c[mt][nt][3] + bias);
                    *(__half2*)(wtsq + r1 * 72 + col) = h;
                }
            }
        }

        // ---- single sync: wts[q] + B(tw+1) become visible; B[q] reads done ----
        CP_WAIT(0);
        __syncthreads();

        // ---- prefetch B(tw+2) into B[q] (safe: all B[q] reads pre-sync) ----
        if (tw < 5) {
            stage_B(tw + 2, q);
            CP_COMMIT();
        }

        // ---- involution(tw): reads wts[q], xs16 ----
        float s0 = 0.f, s1 = 0.f;
#pragma unroll
        for (int ky = 0; ky < 7; ky++) {
            const uint32_t* xrow = (const uint32_t*)(xs16
                + (chw * 14 + phi + ky) * 72 + w0 + pwi);
            uint32_t x01 = xrow[0], x23 = xrow[1], x45 = xrow[2], x67 = xrow[3];
            uint32_t xp[7];
            xp[0] = x01;
            xp[1] = prmt5432(x01, x23);
            xp[2] = x23;
            xp[3] = prmt5432(x23, x45);
            xp[4] = x45;
            xp[5] = prmt5432(x45, x67);
            xp[6] = x67;
            const __half2* wrow = (const __half2*)(wtsq + (ky * 7) * 72) + pp;
            __half2 acc = __floats2half2_rn(0.f, 0.f);
#pragma unroll
            for (int kx = 0; kx < 7; kx++)
                acc = __hfma2(wrow[kx * 36], *(const __half2*)&xp[kx], acc);
            float2 t = __half22float2(acc);
            s0 += t.x;
            s1 += t.y;
        }
        *(float2*)(out + ((size_t)(b * C + g * 4 + chw) * Hdim + h0 + phi) * Hdim
                   + w0 + pwi) = make_float2(s0, s1);
    }
}

extern "C" void kernel_launch(void* const* d_in, const int* in_sizes, int n_in,
                              void* d_out, int out_size)
{
    const float* x     = (const float*)d_in[0];
    const float* w1    = (const float*)d_in[1];
    const float* b1    = (const float*)d_in[2];
    const float* gamma = (const float*)d_in[3];
    const float* beta  = (const float*)d_in[4];
    const float* mean  = (const float*)d_in[5];
    const float* var   = (const float*)d_in[6];
    const float* w2    = (const float*)d_in[7];
    const float* b2    = (const float*)d_in[8];
    float* out = (float*)d_out;

    cudaFuncSetAttribute(k2_involution,
                         cudaFuncAttributeMaxDynamicSharedMemorySize, SMEM_K2);

    dim3 g1(49, 4);
    k1_mma<<<g1, 256>>>(x, w1, b1, gamma, beta, mean, var);

    dim3 g2(7, 4, 64);
    k2_involution<<<g2, 128, SMEM_K2>>>(x, w2, b2, out);
}